// round 2
// baseline (speedup 1.0000x reference)
#include <cuda_runtime.h>

#define Dn 4
#define Cn 64
#define Hn 64
#define Wn 64
#define Nn 4096
#define QKn 32

// ------------------ static device scratch (no runtime allocation) ------------------
__device__ __align__(16) float g_qt[Dn * Nn * QKn];     // q transposed: [d][n][32]
__device__ __align__(16) float g_k [Dn * QKn * Nn];     // k: [d][c][m]
__device__ __align__(16) float g_s [Dn * Nn * Nn];      // raw scores [d][n][m] (256MB)
__device__ float g_mx [Dn * Nn];                        // softmax1 row max
__device__ float g_sum[Dn * Nn];                        // softmax1 row sum

// ------------------ packed f32x2 helpers (Blackwell) ------------------
__device__ __forceinline__ unsigned long long pk2(float a, float b) {
    unsigned long long r;
    asm("mov.b64 %0, {%1,%2};" : "=l"(r) : "f"(a), "f"(b));
    return r;
}
__device__ __forceinline__ float2 upk2(unsigned long long v) {
    float a, b;
    asm("mov.b64 {%0,%1}, %2;" : "=f"(a), "=f"(b) : "l"(v));
    return make_float2(a, b);
}
#define FMA2(d, a, b) asm("fma.rn.f32x2 %0, %1, %2, %0;" : "+l"(d) : "l"(a), "l"(b))
#define MUL2(d, a, b) asm("mul.rn.f32x2 %0, %1, %2;" : "=l"(d) : "l"(a), "l"(b))

// ============================================================================
// K1: 3x3 SAME conv for q and k. grid (H, D, 2proj), 256 thr = 32 oc x 8 wgrp.
// Each thread computes 8 outputs along w for one output channel.
// ============================================================================
__global__ __launch_bounds__(256) void conv_qk(
    const float* __restrict__ x,
    const float* __restrict__ qw, const float* __restrict__ qb,
    const float* __restrict__ kw, const float* __restrict__ kb)
{
    __shared__ float xs[3][16][66];    // (dy, ic_local, w+1), zero side pads
    __shared__ float wsm[16][9][32];   // (ic_local, tap, oc)

    const int h = blockIdx.x, d = blockIdx.y, proj = blockIdx.z;
    const int tid = threadIdx.x;
    const int oc = tid & 31, wg = tid >> 5;

    const float* wsrc = proj ? kw : qw;
    float acc[8];
    {
        float b = proj ? kb[oc] : qb[oc];
#pragma unroll
        for (int j = 0; j < 8; j++) acc[j] = b;
    }

    for (int chunk = 0; chunk < 4; chunk++) {
        for (int i = tid; i < 16 * 64; i += 256) {
            int icl = i >> 6, w = i & 63;
            const float* xp = x + ((size_t)(d * Cn + chunk * 16 + icl)) * (size_t)(Hn * Wn);
#pragma unroll
            for (int dy = 0; dy < 3; dy++) {
                int hh = h + dy - 1;
                xs[dy][icl][w + 1] = (hh >= 0 && hh < Hn) ? xp[hh * Wn + w] : 0.f;
            }
            if (w == 0) {
#pragma unroll
                for (int dy = 0; dy < 3; dy++) { xs[dy][icl][0] = 0.f; xs[dy][icl][65] = 0.f; }
            }
        }
        for (int i = tid; i < 16 * 9 * 32; i += 256) {
            int icl = i / 288, rem = i % 288, tap = rem >> 5, o = rem & 31;
            wsm[icl][tap][o] = wsrc[(o * Cn + chunk * 16 + icl) * 9 + tap];
        }
        __syncthreads();

        for (int icl = 0; icl < 16; icl++) {
#pragma unroll
            for (int dy = 0; dy < 3; dy++) {
                float xv[10];
#pragma unroll
                for (int t = 0; t < 10; t++) xv[t] = xs[dy][icl][wg * 8 + t];
#pragma unroll
                for (int dx = 0; dx < 3; dx++) {
                    float wv = wsm[icl][dy * 3 + dx][oc];
#pragma unroll
                    for (int j = 0; j < 8; j++) acc[j] = fmaf(wv, xv[dx + j], acc[j]);
                }
            }
        }
        __syncthreads();
    }

    const int n = h * Wn + wg * 8;
    if (proj == 0) {
#pragma unroll
        for (int j = 0; j < 8; j++)
            g_qt[((size_t)(d * Nn + n + j)) * QKn + oc] = acc[j];
    } else {
#pragma unroll
        for (int j = 0; j < 8; j++)
            g_k[((size_t)(d * QKn + oc)) * Nn + n + j] = acc[j];
    }
}

// ============================================================================
// K2: scores s[d,n,m] = sum_c q[n,c] k[c,m]; write raw scores; online softmax1
// row stats. grid (N/32, D), 256 thr. warp w owns rows 4w..4w+3; lane owns
// m-quad lane*4 within a 128-m tile. f32x2 inner product.
// ============================================================================
__global__ __launch_bounds__(256) void qk_scores()
{
    __shared__ float qs2[32][64];      // [r][2c+{0,1}] q duplicated pairs
    __shared__ float4 ks[32][32];      // [c][m_quad]

    const int d = blockIdx.y, n0 = blockIdx.x * 32;
    const int tid = threadIdx.x, lane = tid & 31, warp = tid >> 5;

    {
        const float* qsrc = g_qt + ((size_t)(d * Nn + n0)) * QKn;
        float4 qv = ((const float4*)qsrc)[tid];     // 32 rows x 8 quads
        int r = tid >> 3, cb = (tid & 7) * 4;
        qs2[r][(cb + 0) * 2] = qv.x; qs2[r][(cb + 0) * 2 + 1] = qv.x;
        qs2[r][(cb + 1) * 2] = qv.y; qs2[r][(cb + 1) * 2 + 1] = qv.y;
        qs2[r][(cb + 2) * 2] = qv.z; qs2[r][(cb + 2) * 2 + 1] = qv.z;
        qs2[r][(cb + 3) * 2] = qv.w; qs2[r][(cb + 3) * 2 + 1] = qv.w;
    }

    float mx[4], sm[4];
#pragma unroll
    for (int i = 0; i < 4; i++) { mx[i] = -1e30f; sm[i] = 0.f; }
    const int r0 = warp * 4;

    for (int mt = 0; mt < Nn / 128; mt++) {
        const int m0 = mt * 128;
        __syncthreads();
        for (int i = tid; i < 1024; i += 256) {
            int c = i >> 5, mq = i & 31;
            ks[c][mq] = *(const float4*)(g_k + ((size_t)(d * QKn + c)) * Nn + m0 + mq * 4);
        }
        __syncthreads();

        unsigned long long a0[4], a1[4];
#pragma unroll
        for (int i = 0; i < 4; i++) { a0[i] = 0ull; a1[i] = 0ull; }

#pragma unroll
        for (int c = 0; c < 32; c++) {
            ulonglong2 kv = *(const ulonglong2*)&ks[c][lane];
#pragma unroll
            for (int i = 0; i < 4; i++) {
                unsigned long long qp = *(const unsigned long long*)&qs2[r0 + i][c * 2];
                FMA2(a0[i], qp, kv.x);
                FMA2(a1[i], qp, kv.y);
            }
        }

#pragma unroll
        for (int i = 0; i < 4; i++) {
            float2 p0 = upk2(a0[i]), p1 = upk2(a1[i]);
            *(float4*)(g_s + ((size_t)(d * Nn + n0 + r0 + i)) * Nn + m0 + lane * 4)
                = make_float4(p0.x, p0.y, p1.x, p1.y);
            float tm = fmaxf(fmaxf(p0.x, p0.y), fmaxf(p1.x, p1.y));
#pragma unroll
            for (int o = 16; o > 0; o >>= 1)
                tm = fmaxf(tm, __shfl_xor_sync(0xffffffffu, tm, o));
            float nm = fmaxf(mx[i], tm);
            float es = __expf(p0.x - nm) + __expf(p0.y - nm)
                     + __expf(p1.x - nm) + __expf(p1.y - nm);
#pragma unroll
            for (int o = 16; o > 0; o >>= 1)
                es += __shfl_xor_sync(0xffffffffu, es, o);
            sm[i] = sm[i] * __expf(mx[i] - nm) + es;
            mx[i] = nm;
        }
    }

    if (lane == 0) {
#pragma unroll
        for (int i = 0; i < 4; i++) {
            g_mx [d * Nn + n0 + r0 + i] = mx[i];
            g_sum[d * Nn + n0 + r0 + i] = sm[i];
        }
    }
}

// ============================================================================
// K3: t = softmax1(s) + atten; online softmax2; out = gamma*(P @ V^T)/sum + x.
// grid (N/32, D), 256 thr. 64-m tiles. GEMM thread = 2 n-rows x 4 c-chans.
// ============================================================================
__global__ __launch_bounds__(256) void attn_v(
    const float* __restrict__ x, const float* __restrict__ atten,
    const float* __restrict__ gamma, float* __restrict__ out)
{
    __shared__ float ts[64 * 34];      // t / e transposed: [m][n], pad 34
    __shared__ float vs[64 * 68];      // v tile: [m][c], pad 68
    __shared__ float mx1[32], is1[32], m2s[32], sum2s[32], scls[32];

    const int d = blockIdx.y;
    const int gn0 = blockIdx.x * 32;
    const int tid = threadIdx.x;
    const int lane = tid & 31, warp = tid >> 5;

    if (tid < 32) {
        mx1[tid] = g_mx[d * Nn + gn0 + tid];
        is1[tid] = 1.0f / g_sum[d * Nn + gn0 + tid];
        m2s[tid] = -1e30f;
        sum2s[tid] = 0.f;
    }

    const int cq = tid & 15, np = tid >> 4;
    const int c0 = cq * 4, n0 = np * 2;
    unsigned long long acc00 = 0, acc01 = 0, acc10 = 0, acc11 = 0;

    const int an = tid >> 4;       // phase A: rows an, an+16
    const int amq = tid & 15;      // m-quad

    for (int m0 = 0; m0 < Nn; m0 += 64) {
        __syncthreads();   // previous GEMM done before overwriting ts/vs

        // --- phase A: t tile -> ts[m][n] (transposed) ---
#pragma unroll
        for (int kk = 0; kk < 2; kk++) {
            int n = an + 16 * kk;
            size_t base = ((size_t)(d * Nn + gn0 + n)) * Nn + m0 + amq * 4;
            float4 s4 = *(const float4*)(g_s + base);
            float4 a4 = *(const float4*)(atten + base);
            float mr = mx1[n], ir = is1[n];
            ts[(amq * 4 + 0) * 34 + n] = __expf(s4.x - mr) * ir + a4.x;
            ts[(amq * 4 + 1) * 34 + n] = __expf(s4.y - mr) * ir + a4.y;
            ts[(amq * 4 + 2) * 34 + n] = __expf(s4.z - mr) * ir + a4.z;
            ts[(amq * 4 + 3) * 34 + n] = __expf(s4.w - mr) * ir + a4.w;
        }
        // --- v tile -> vs[m][c] (transposed) ---
#pragma unroll
        for (int k = 0; k < 4; k++) {
            int i = tid + 256 * k;
            int cv = i >> 6;           // c-quad 0..15
            int m = i & 63;
            const float* xp = x + ((size_t)(d * Cn + cv * 4)) * Nn + m0 + m;
            float4 v;
            v.x = xp[0]; v.y = xp[Nn]; v.z = xp[2 * Nn]; v.w = xp[3 * Nn];
            *(float4*)&vs[m * 68 + cv * 4] = v;
        }
        __syncthreads();

        // --- phase B: online softmax2, warp w owns rows 4w..4w+3 ---
        {
            float t0[4], t1[4], tm[4];
#pragma unroll
            for (int i = 0; i < 4; i++) {
                int r = warp * 4 + i;
                t0[i] = ts[lane * 34 + r];
                t1[i] = ts[(lane + 32) * 34 + r];
                tm[i] = fmaxf(t0[i], t1[i]);
            }
#pragma unroll
            for (int o = 16; o > 0; o >>= 1) {
#pragma unroll
                for (int i = 0; i < 4; i++)
                    tm[i] = fmaxf(tm[i], __shfl_xor_sync(0xffffffffu, tm[i], o));
            }
            float es[4], nm[4], sc[4];
#pragma unroll
            for (int i = 0; i < 4; i++) {
                int r = warp * 4 + i;
                nm[i] = fmaxf(m2s[r], tm[i]);
                sc[i] = __expf(m2s[r] - nm[i]);
                float e0 = __expf(t0[i] - nm[i]);
                float e1 = __expf(t1[i] - nm[i]);
                ts[lane * 34 + r] = e0;
                ts[(lane + 32) * 34 + r] = e1;
                es[i] = e0 + e1;
            }
#pragma unroll
            for (int o = 16; o > 0; o >>= 1) {
#pragma unroll
                for (int i = 0; i < 4; i++)
                    es[i] += __shfl_xor_sync(0xffffffffu, es[i], o);
            }
            if (lane == 0) {
#pragma unroll
                for (int i = 0; i < 4; i++) {
                    int r = warp * 4 + i;
                    sum2s[r] = sum2s[r] * sc[i] + es[i];
                    m2s[r] = nm[i];
                    scls[r] = sc[i];
                }
            }
        }
        __syncthreads();

        // --- phase C: rescale accumulators, f32x2 GEMM over this m tile ---
        {
            float sa = scls[n0], sb = scls[n0 + 1];
            unsigned long long s2a = pk2(sa, sa), s2b = pk2(sb, sb);
            MUL2(acc00, acc00, s2a); MUL2(acc01, acc01, s2a);
            MUL2(acc10, acc10, s2b); MUL2(acc11, acc11, s2b);
#pragma unroll 8
            for (int m = 0; m < 64; m++) {
                float2 e2 = *(const float2*)&ts[m * 34 + n0];
                ulonglong2 v2 = *(const ulonglong2*)&vs[m * 68 + c0];
                unsigned long long ex = pk2(e2.x, e2.x);
                unsigned long long ey = pk2(e2.y, e2.y);
                FMA2(acc00, v2.x, ex); FMA2(acc01, v2.y, ex);
                FMA2(acc10, v2.x, ey); FMA2(acc11, v2.y, ey);
            }
        }
    }

    // --- epilogue: out = gamma * acc / sum2 + x ---
    {
        float g = gamma[0];
        float inv0 = 1.0f / sum2s[n0];
        float inv1 = 1.0f / sum2s[n0 + 1];
        float2 p00 = upk2(acc00), p01 = upk2(acc01);
        float2 p10 = upk2(acc10), p11 = upk2(acc11);
        float r0v[4] = {p00.x, p00.y, p01.x, p01.y};
        float r1v[4] = {p10.x, p10.y, p11.x, p11.y};
#pragma unroll
        for (int cc = 0; cc < 4; cc++) {
            size_t i0 = ((size_t)(d * Cn + c0 + cc)) * Nn + gn0 + n0;
            out[i0]     = g * r0v[cc] * inv0 + x[i0];
            out[i0 + 1] = g * r1v[cc] * inv1 + x[i0 + 1];
        }
    }
}

// ============================================================================
extern "C" void kernel_launch(void* const* d_in, const int* in_sizes, int n_in,
                              void* d_out, int out_size)
{
    const float* x   = (const float*)d_in[0];
    const float* att = (const float*)d_in[1];
    const float* qw  = (const float*)d_in[2];
    const float* qb  = (const float*)d_in[3];
    const float* kw  = (const float*)d_in[4];
    const float* kb  = (const float*)d_in[5];
    const float* gm  = (const float*)d_in[6];
    float* out = (float*)d_out;

    conv_qk  <<<dim3(Hn, Dn, 2), 256>>>(x, qw, qb, kw, kb);
    qk_scores<<<dim3(Nn / 32, Dn), 256>>>();
    attn_v   <<<dim3(Nn / 32, Dn), 256>>>(x, att, gm, out);
}